// round 10
// baseline (speedup 1.0000x reference)
#include <cuda_runtime.h>

// BSplineLayer: piecewise-linear spline eval.
// u: [4096, 64, 256] f32 (flat, channel = i % 256)
// knots: [256, 64] sorted ascending per channel; coefs: [256, 64].
// out = c0 + (x-k0)/(k1-k0+1e-6) * (c1-c0), segment via searchsorted-left.
//
// R10 = R9 (conflict-free permuted fp32 table, 1024x1, 8 consecutive elems)
// + software-pipelined prefetch: next iteration's 2 LDG.128 are issued before
//   computing the current one -> 4 LDG.128 in flight per warp (2x MLP),
//   attacking the measured binder (exposed DRAM latency; nothing saturated).
// + scale folded into table dc (fp32, ~1ulp) to free registers for the
//   double buffer: params 16 regs instead of 24.
// + __ldcs/__stcs streaming hints on u/out.

#define M_CH    256
#define K_KNOTS 64
#define N_SEG   63
#define EPS     1e-6f

#define COLP(c) (((c) >> 3) + (((c) & 7) << 5))

// smem: float2 sparam[256] (invh, b) | float2 sseg[64*256] permuted | int flag
#define SMEM_BYTES (256 * 8 + 64 * 256 * 8 + 16)

__global__ __launch_bounds__(1024, 1)
void bspline_kernel(const float* __restrict__ u,
                    const float* __restrict__ knots,
                    const float* __restrict__ coefs,
                    float* __restrict__ out,
                    int n8 /* groups of 8 elements */)
{
    extern __shared__ char smem_raw[];
    float2* sparam = (float2*)smem_raw;                      // [256] (invh, b)
    float2* sseg   = (float2*)(smem_raw + 256 * 8);          // [64][256] (c0, dc*scale)
    int*    sflag  = (int*)(smem_raw + 256 * 8 + 64 * 256 * 8);

    const int tid = threadIdx.x;

    if (tid == 0) *sflag = 0;
    __syncthreads();

    // ---- stage coef segments, permuted, scale folded into dc ----
    for (int i = tid; i < M_CH * K_KNOTS; i += blockDim.x) {
        int j = i & 63;
        if (j < N_SEG) {
            int c = i >> 6;
            float k0 = knots[c * K_KNOTS];
            float kl = knots[c * K_KNOTS + K_KNOTS - 1];
            float h  = (kl - k0) * (1.0f / (float)N_SEG);
            float scale = h / (h + EPS);
            float c0 = coefs[c * K_KNOTS + j];
            float c1 = coefs[c * K_KNOTS + j + 1];
            sseg[(j << 8) + COLP(c)] = make_float2(c0, (c1 - c0) * scale);
        }
    }

    // ---- per-channel affine params + uniformity check ----
    if (tid < M_CH) {
        const int c = tid;
        const float* kc = knots + c * K_KNOTS;
        float k0 = kc[0];
        float kl = kc[K_KNOTS - 1];
        float h  = (kl - k0) * (1.0f / (float)N_SEG);
        float invh = (float)N_SEG / (kl - k0);
        float tol = 1e-4f * fabsf(h) + 1e-30f;
        bool bad = !(h > 0.0f);
        #pragma unroll 4
        for (int j = 1; j < K_KNOTS - 1; j++) {
            float pred = fmaf((float)j, h, k0);
            if (fabsf(kc[j] - pred) > tol) { bad = true; break; }
        }
        if (bad) *sflag = 1;
        sparam[c] = make_float2(invh, -k0 * invh);
    }
    __syncthreads();

    const bool affine = (*sflag == 0);

    const float4* __restrict__ u4 = (const float4*)u;
    float4*       __restrict__ o4 = (float4*)out;
    const int gtid   = blockIdx.x * blockDim.x + tid;
    const int stride = blockDim.x * gridDim.x;   // group stride; 8*stride % 256 == 0
    const int cb     = (gtid * 8) & (M_CH - 1);  // channels cb..cb+7, fixed

    if (affine) {
        // preload 8 channel params (invh, b) -> 16 registers
        float p_invh[8], p_b[8];
        #pragma unroll
        for (int i = 0; i < 8; i++) {
            float2 p = sparam[cb + i];
            p_invh[i] = p.x; p_b[i] = p.y;
        }
        const float2* __restrict__ seg0 = sseg + (cb >> 3);

        int t = gtid;
        if (t < n8) {
            // prologue: first pair of loads
            float4 a = __ldcs(u4 + 2 * t);
            float4 b = __ldcs(u4 + 2 * t + 1);

            // pipelined main loop: prefetch (t+stride) before computing t
            for (; t + stride < n8; t += stride) {
                float4 an = __ldcs(u4 + 2 * (t + stride));
                float4 bn = __ldcs(u4 + 2 * (t + stride) + 1);

                float x[8] = {a.x, a.y, a.z, a.w, b.x, b.y, b.z, b.w};
                float r[8];
                #pragma unroll
                for (int i = 0; i < 8; i++) {
                    float s  = fmaf(x[i], p_invh[i], p_b[i]);
                    float jf = floorf(s);
                    jf = fminf(fmaxf(jf, 0.0f), (float)(N_SEG - 1));
                    int  ji = (int)jf;
                    float2 cd = seg0[(ji << 8) + (i << 5)];   // conflict-free LDS.64
                    r[i] = fmaf(s - jf, cd.y, cd.x);
                }
                __stcs(o4 + 2 * t,     make_float4(r[0], r[1], r[2], r[3]));
                __stcs(o4 + 2 * t + 1, make_float4(r[4], r[5], r[6], r[7]));

                a = an; b = bn;
            }
            // epilogue: last group
            {
                float x[8] = {a.x, a.y, a.z, a.w, b.x, b.y, b.z, b.w};
                float r[8];
                #pragma unroll
                for (int i = 0; i < 8; i++) {
                    float s  = fmaf(x[i], p_invh[i], p_b[i]);
                    float jf = floorf(s);
                    jf = fminf(fmaxf(jf, 0.0f), (float)(N_SEG - 1));
                    int  ji = (int)jf;
                    float2 cd = seg0[(ji << 8) + (i << 5)];
                    r[i] = fmaf(s - jf, cd.y, cd.x);
                }
                __stcs(o4 + 2 * t,     make_float4(r[0], r[1], r[2], r[3]));
                __stcs(o4 + 2 * t + 1, make_float4(r[4], r[5], r[6], r[7]));
            }
        }
    } else {
        // generic fallback: exact searchsorted-left via binary search, f32 math
        for (int t = gtid; t < n8; t += stride) {
            float4 a = u4[2 * t];
            float4 b = u4[2 * t + 1];
            float x[8] = {a.x, a.y, a.z, a.w, b.x, b.y, b.z, b.w};
            float r[8];
            #pragma unroll
            for (int i = 0; i < 8; i++) {
                const int c = cb + i;
                const float* kc = knots + c * K_KNOTS;
                const float xi = x[i];
                int lo = 0, hi = K_KNOTS;
                while (lo < hi) {
                    int mid = (lo + hi) >> 1;
                    if (__ldg(kc + mid) < xi) lo = mid + 1; else hi = mid;
                }
                int j = min(max(lo - 1, 0), N_SEG - 1);
                float k0 = __ldg(kc + j);
                float k1 = __ldg(kc + j + 1);
                float c0 = __ldg(coefs + c * K_KNOTS + j);
                float c1 = __ldg(coefs + c * K_KNOTS + j + 1);
                float tt = (xi - k0) / (k1 - k0 + EPS);
                r[i] = fmaf(tt, c1 - c0, c0);
            }
            o4[2 * t]     = make_float4(r[0], r[1], r[2], r[3]);
            o4[2 * t + 1] = make_float4(r[4], r[5], r[6], r[7]);
        }
    }
}

extern "C" void kernel_launch(void* const* d_in, const int* in_sizes, int n_in,
                              void* d_out, int out_size)
{
    const float* u     = (const float*)d_in[0];
    const float* knots = (const float*)d_in[1];
    const float* coefs = (const float*)d_in[2];
    float*       out   = (float*)d_out;

    const int n  = in_sizes[0];   // 67,108,864 (divisible by 8)
    const int n8 = n >> 3;

    static_assert(SMEM_BYTES <= 227 * 1024, "smem over sm_103a limit");
    cudaFuncSetAttribute(bspline_kernel,
                         cudaFuncAttributeMaxDynamicSharedMemorySize, SMEM_BYTES);

    int dev = 0, nsm = 148;
    cudaGetDevice(&dev);
    cudaDeviceGetAttribute(&nsm, cudaDevAttrMultiProcessorCount, dev);

    bspline_kernel<<<nsm, 1024, SMEM_BYTES>>>(u, knots, coefs, out, n8);
}

// round 11
// speedup vs baseline: 1.0412x; 1.0412x over previous
#include <cuda_runtime.h>

// BSplineLayer: piecewise-linear spline eval.
// u: [4096, 64, 256] f32 (flat, channel = i % 256)
// knots: [256, 64] sorted ascending per channel; coefs: [256, 64].
// out = c0 + (x-k0)/(k1-k0+1e-6) * (c1-c0), segment via searchsorted-left.
//
// R11 = R9 (best: conflict-free permuted fp32 table, 1024x1 CTA, 8
// consecutive elements per thread, 2 front-batched LDG.128) with scale
// folded into the table's dc (saves 1 FMUL/elem and 8 registers). No
// prefetch, no streaming hints (both measured neutral/negative in R10).
// Evidence says we sit ~3% off the combined-LTS traffic wall (~1073MB
// read+write at ~10.5 TB/s): this is a convergence round.

#define M_CH    256
#define K_KNOTS 64
#define N_SEG   63
#define EPS     1e-6f

#define COLP(c) (((c) >> 3) + (((c) & 7) << 5))

// smem: float2 sparam[256] (invh, b) | float2 sseg[64*256] permuted | int flag
#define SMEM_BYTES (256 * 8 + 64 * 256 * 8 + 16)

__global__ __launch_bounds__(1024, 1)
void bspline_kernel(const float* __restrict__ u,
                    const float* __restrict__ knots,
                    const float* __restrict__ coefs,
                    float* __restrict__ out,
                    int n8 /* groups of 8 elements */)
{
    extern __shared__ char smem_raw[];
    float2* sparam = (float2*)smem_raw;                      // [256] (invh, b)
    float2* sseg   = (float2*)(smem_raw + 256 * 8);          // [64][256] (c0, dc*scale)
    int*    sflag  = (int*)(smem_raw + 256 * 8 + 64 * 256 * 8);

    const int tid = threadIdx.x;

    if (tid == 0) *sflag = 0;
    __syncthreads();

    // ---- stage coef segments, permuted, scale folded into dc ----
    // sseg[(j<<8)+COLP(c)] = (c_j, (c_{j+1}-c_j) * h/(h+eps))
    for (int i = tid; i < M_CH * K_KNOTS; i += blockDim.x) {
        int j = i & 63;
        if (j < N_SEG) {
            int c = i >> 6;
            float k0 = knots[c * K_KNOTS];
            float kl = knots[c * K_KNOTS + K_KNOTS - 1];
            float h  = (kl - k0) * (1.0f / (float)N_SEG);
            float scale = h / (h + EPS);
            float c0 = coefs[c * K_KNOTS + j];
            float c1 = coefs[c * K_KNOTS + j + 1];
            sseg[(j << 8) + COLP(c)] = make_float2(c0, (c1 - c0) * scale);
        }
    }

    // ---- per-channel affine params + uniformity check ----
    if (tid < M_CH) {
        const int c = tid;
        const float* kc = knots + c * K_KNOTS;
        float k0 = kc[0];
        float kl = kc[K_KNOTS - 1];
        float h  = (kl - k0) * (1.0f / (float)N_SEG);
        float invh = (float)N_SEG / (kl - k0);
        float tol = 1e-4f * fabsf(h) + 1e-30f;
        bool bad = !(h > 0.0f);
        #pragma unroll 4
        for (int j = 1; j < K_KNOTS - 1; j++) {
            float pred = fmaf((float)j, h, k0);
            if (fabsf(kc[j] - pred) > tol) { bad = true; break; }
        }
        if (bad) *sflag = 1;
        sparam[c] = make_float2(invh, -k0 * invh);
    }
    __syncthreads();

    const bool affine = (*sflag == 0);

    const float4* __restrict__ u4 = (const float4*)u;
    float4*       __restrict__ o4 = (float4*)out;
    const int gtid   = blockIdx.x * blockDim.x + tid;
    const int stride = blockDim.x * gridDim.x;   // group stride; 8*stride % 256 == 0
    const int cb     = (gtid * 8) & (M_CH - 1);  // channels cb..cb+7, fixed

    if (affine) {
        // preload this thread's 8 channel params (invh, b) -> 16 registers
        float p_invh[8], p_b[8];
        #pragma unroll
        for (int i = 0; i < 8; i++) {
            float2 p = sparam[cb + i];
            p_invh[i] = p.x; p_b[i] = p.y;
        }
        // permuted table base: + (i<<5) + (j<<8) per access; bank-pair = 2*lane
        const float2* __restrict__ seg0 = sseg + (cb >> 3);

        for (int t = gtid; t < n8; t += stride) {
            float4 a = u4[2 * t];
            float4 b = u4[2 * t + 1];
            float x[8] = {a.x, a.y, a.z, a.w, b.x, b.y, b.z, b.w};
            float r[8];
            #pragma unroll
            for (int i = 0; i < 8; i++) {
                float s  = fmaf(x[i], p_invh[i], p_b[i]);
                float jf = floorf(s);
                jf = fminf(fmaxf(jf, 0.0f), (float)(N_SEG - 1));
                int  ji = (int)jf;
                float2 cd = seg0[(ji << 8) + (i << 5)];   // conflict-free LDS.64
                r[i] = fmaf(s - jf, cd.y, cd.x);
            }
            o4[2 * t]     = make_float4(r[0], r[1], r[2], r[3]);
            o4[2 * t + 1] = make_float4(r[4], r[5], r[6], r[7]);
        }
    } else {
        // generic fallback: exact searchsorted-left via binary search, f32 math
        for (int t = gtid; t < n8; t += stride) {
            float4 a = u4[2 * t];
            float4 b = u4[2 * t + 1];
            float x[8] = {a.x, a.y, a.z, a.w, b.x, b.y, b.z, b.w};
            float r[8];
            #pragma unroll
            for (int i = 0; i < 8; i++) {
                const int c = cb + i;
                const float* kc = knots + c * K_KNOTS;
                const float xi = x[i];
                int lo = 0, hi = K_KNOTS;
                while (lo < hi) {
                    int mid = (lo + hi) >> 1;
                    if (__ldg(kc + mid) < xi) lo = mid + 1; else hi = mid;
                }
                int j = min(max(lo - 1, 0), N_SEG - 1);
                float k0 = __ldg(kc + j);
                float k1 = __ldg(kc + j + 1);
                float c0 = __ldg(coefs + c * K_KNOTS + j);
                float c1 = __ldg(coefs + c * K_KNOTS + j + 1);
                float tt = (xi - k0) / (k1 - k0 + EPS);
                r[i] = fmaf(tt, c1 - c0, c0);
            }
            o4[2 * t]     = make_float4(r[0], r[1], r[2], r[3]);
            o4[2 * t + 1] = make_float4(r[4], r[5], r[6], r[7]);
        }
    }
}

extern "C" void kernel_launch(void* const* d_in, const int* in_sizes, int n_in,
                              void* d_out, int out_size)
{
    const float* u     = (const float*)d_in[0];
    const float* knots = (const float*)d_in[1];
    const float* coefs = (const float*)d_in[2];
    float*       out   = (float*)d_out;

    const int n  = in_sizes[0];   // 67,108,864 (divisible by 8)
    const int n8 = n >> 3;

    static_assert(SMEM_BYTES <= 227 * 1024, "smem over sm_103a limit");
    cudaFuncSetAttribute(bspline_kernel,
                         cudaFuncAttributeMaxDynamicSharedMemorySize, SMEM_BYTES);

    int dev = 0, nsm = 148;
    cudaGetDevice(&dev);
    cudaDeviceGetAttribute(&nsm, cudaDevAttrMultiProcessorCount, dev);

    bspline_kernel<<<nsm, 1024, SMEM_BYTES>>>(u, knots, coefs, out, n8);
}

// round 12
// speedup vs baseline: 1.0784x; 1.0357x over previous
#include <cuda_runtime.h>

// BSplineLayer: piecewise-linear spline eval.
// u: [4096, 64, 256] f32 (flat, channel = i % 256)
// knots: [256, 64] sorted ascending per channel; coefs: [256, 64].
// out = c0 + (x-k0)/(k1-k0+1e-6) * (c1-c0), segment via searchsorted-left.
//
// Final form. Evidence across R3/R9/R10/R11: kernel sits at the combined
// L2-traffic floor (1072 MB compulsory @ ~10.5 TB/s LTS cap ~= 102 us ncu);
// conflicts fixed (flat), MLP doubled (flat), warps raised (worse).
// R12 = R9's mainloop (conflict-free permuted fp32 table, 1024x1 CTA,
// 8 consecutive elems/thread, 2 front-batched LDG.128, separate scale for
// best rel_err) + fully parallel prologue (uniformity check fused into the
// staging loop; removes the ~2us serial 62-load chain under the barrier).

#define M_CH    256
#define K_KNOTS 64
#define N_SEG   63
#define EPS     1e-6f

#define COLP(c) (((c) >> 3) + (((c) & 7) << 5))

// smem: float4 sparam[256] | float2 sseg[64*256] permuted | int flag
#define SMEM_BYTES (256 * 16 + 64 * 256 * 8 + 16)

__global__ __launch_bounds__(1024, 1)
void bspline_kernel(const float* __restrict__ u,
                    const float* __restrict__ knots,
                    const float* __restrict__ coefs,
                    float* __restrict__ out,
                    int n8 /* groups of 8 elements */)
{
    extern __shared__ char smem_raw[];
    float4* sparam = (float4*)smem_raw;                       // [256] (invh, b, scale, 0)
    float2* sseg   = (float2*)(smem_raw + 256 * 16);          // [64][256] permuted (c0, dc)
    int*    sflag  = (int*)(smem_raw + 256 * 16 + 64 * 256 * 8);

    const int tid = threadIdx.x;

    if (tid == 0) *sflag = 0;
    __syncthreads();

    // ---- fused staging + fully parallel uniformity check ----
    // one work-item per (c, j): stage sseg[(j<<8)+COLP(c)] and verify
    // knots[c,j] against the channel's affine prediction (independent loads).
    bool bad = false;
    for (int i = tid; i < M_CH * K_KNOTS; i += blockDim.x) {
        int c = i >> 6;
        int j = i & 63;
        float kj = knots[i];
        float k0 = knots[c * K_KNOTS];
        float kl = knots[c * K_KNOTS + K_KNOTS - 1];
        float h  = (kl - k0) * (1.0f / (float)N_SEG);
        float tol = 1e-4f * fabsf(h) + 1e-30f;
        float pred = fmaf((float)j, h, k0);
        if (!(h > 0.0f) || fabsf(kj - pred) > tol) bad = true;
        if (j < N_SEG) {
            float c0 = coefs[c * K_KNOTS + j];
            float c1 = coefs[c * K_KNOTS + j + 1];
            sseg[(j << 8) + COLP(c)] = make_float2(c0, c1 - c0);
        }
        if (j == 0) {  // one writer per channel for params
            float invh = (float)N_SEG / (kl - k0);
            float scale = h / (h + EPS);
            sparam[c] = make_float4(invh, -k0 * invh, scale, 0.0f);
        }
    }
    if (bad) *sflag = 1;       // only 1s written after the 0-init barrier
    __syncthreads();

    const bool affine = (*sflag == 0);

    const float4* __restrict__ u4 = (const float4*)u;
    float4*       __restrict__ o4 = (float4*)out;
    const int gtid   = blockIdx.x * blockDim.x + tid;
    const int stride = blockDim.x * gridDim.x;   // group stride; 8*stride % 256 == 0
    const int cb     = (gtid * 8) & (M_CH - 1);  // channels cb..cb+7, fixed

    if (affine) {
        // preload this thread's 8 channel params into registers
        float p_invh[8], p_b[8], p_scale[8];
        #pragma unroll
        for (int i = 0; i < 8; i++) {
            float4 p = sparam[cb + i];
            p_invh[i] = p.x; p_b[i] = p.y; p_scale[i] = p.z;
        }
        // permuted table base: + (i<<5) + (j<<8) per access; bank-pair = 2*lane
        const float2* __restrict__ seg0 = sseg + (cb >> 3);

        for (int t = gtid; t < n8; t += stride) {
            float4 a = u4[2 * t];
            float4 b = u4[2 * t + 1];
            float x[8] = {a.x, a.y, a.z, a.w, b.x, b.y, b.z, b.w};
            float r[8];
            #pragma unroll
            for (int i = 0; i < 8; i++) {
                float s  = fmaf(x[i], p_invh[i], p_b[i]);
                float jf = floorf(s);
                jf = fminf(fmaxf(jf, 0.0f), (float)(N_SEG - 1));
                int  ji = (int)jf;
                float2 cd = seg0[(ji << 8) + (i << 5)];   // conflict-free LDS.64
                float tt = (s - jf) * p_scale[i];
                r[i] = fmaf(tt, cd.y, cd.x);
            }
            o4[2 * t]     = make_float4(r[0], r[1], r[2], r[3]);
            o4[2 * t + 1] = make_float4(r[4], r[5], r[6], r[7]);
        }
    } else {
        // generic fallback: exact searchsorted-left via binary search, f32 math
        for (int t = gtid; t < n8; t += stride) {
            float4 a = u4[2 * t];
            float4 b = u4[2 * t + 1];
            float x[8] = {a.x, a.y, a.z, a.w, b.x, b.y, b.z, b.w};
            float r[8];
            #pragma unroll
            for (int i = 0; i < 8; i++) {
                const int c = cb + i;
                const float* kc = knots + c * K_KNOTS;
                const float xi = x[i];
                int lo = 0, hi = K_KNOTS;
                while (lo < hi) {
                    int mid = (lo + hi) >> 1;
                    if (__ldg(kc + mid) < xi) lo = mid + 1; else hi = mid;
                }
                int j = min(max(lo - 1, 0), N_SEG - 1);
                float k0 = __ldg(kc + j);
                float k1 = __ldg(kc + j + 1);
                float2 cd = sseg[(j << 8) + COLP(c)];
                float tt = (xi - k0) / (k1 - k0 + EPS);
                r[i] = fmaf(tt, cd.y, cd.x);
            }
            o4[2 * t]     = make_float4(r[0], r[1], r[2], r[3]);
            o4[2 * t + 1] = make_float4(r[4], r[5], r[6], r[7]);
        }
    }
}

extern "C" void kernel_launch(void* const* d_in, const int* in_sizes, int n_in,
                              void* d_out, int out_size)
{
    const float* u     = (const float*)d_in[0];
    const float* knots = (const float*)d_in[1];
    const float* coefs = (const float*)d_in[2];
    float*       out   = (float*)d_out;

    const int n  = in_sizes[0];   // 67,108,864 (divisible by 8)
    const int n8 = n >> 3;

    static_assert(SMEM_BYTES <= 227 * 1024, "smem over sm_103a limit");
    cudaFuncSetAttribute(bspline_kernel,
                         cudaFuncAttributeMaxDynamicSharedMemorySize, SMEM_BYTES);

    int dev = 0, nsm = 148;
    cudaGetDevice(&dev);
    cudaDeviceGetAttribute(&nsm, cudaDevAttrMultiProcessorCount, dev);

    bspline_kernel<<<nsm, 1024, SMEM_BYTES>>>(u, knots, coefs, out, n8);
}

// round 13
// speedup vs baseline: 1.0961x; 1.0164x over previous
#include <cuda_runtime.h>

// BSplineLayer: piecewise-linear spline eval.
// u: [4096, 64, 256] f32 (flat, channel = i % 256)
// knots: [256, 64] sorted ascending per channel; coefs: [256, 64].
// out = c0 + (x-k0)/(k1-k0+1e-6) * (c1-c0), segment via searchsorted-left.
//
// TERMINAL FORM. Measured: 1072 MB compulsory L2 traffic / 100.7us ncu
// = 10.65 TB/s = the sm_103a path-independent LTS cap. All levers closed:
// LDS conflicts fixed (flat), per-warp MLP doubled (flat), warp count
// raised (worse), instruction count reduced (flat), prologue parallelized
// (-2us). R13 = R12 with prologue load-path polish only.
//
// Structure: conflict-free permuted fp32 table sseg[(j<<8)+COLP(c)]
// (LDS.64 bank-pair = 2*lane, independent of data-dependent j), 1024x1
// CTA/SM, 8 consecutive elements per thread via 2 front-batched LDG.128,
// registers hold the 8 per-channel affine params; exact binary-search
// fallback if knots are not affine.

#define M_CH    256
#define K_KNOTS 64
#define N_SEG   63
#define EPS     1e-6f

#define COLP(c) (((c) >> 3) + (((c) & 7) << 5))

// smem: float4 sparam[256] | float2 sseg[64*256] permuted | int flag
#define SMEM_BYTES (256 * 16 + 64 * 256 * 8 + 16)

__global__ __launch_bounds__(1024, 1)
void bspline_kernel(const float* __restrict__ u,
                    const float* __restrict__ knots,
                    const float* __restrict__ coefs,
                    float* __restrict__ out,
                    int n8 /* groups of 8 elements */)
{
    extern __shared__ char smem_raw[];
    float4* sparam = (float4*)smem_raw;                       // [256] (invh, b, scale, 0)
    float2* sseg   = (float2*)(smem_raw + 256 * 16);          // [64][256] permuted (c0, dc)
    int*    sflag  = (int*)(smem_raw + 256 * 16 + 64 * 256 * 8);

    const int tid = threadIdx.x;

    if (tid == 0) *sflag = 0;
    __syncthreads();

    // ---- fused staging + fully parallel uniformity check ----
    // one work-item per (c, j): stage sseg[(j<<8)+COLP(c)] and verify
    // knots[c,j] against the channel's affine prediction. All loads issued
    // independently up front (kj, k0, kl, c0, c1) -> two latency rounds.
    bool bad = false;
    for (int i = tid; i < M_CH * K_KNOTS; i += blockDim.x) {
        int c = i >> 6;
        int j = i & 63;
        float kj = __ldg(knots + i);
        float k0 = __ldg(knots + c * K_KNOTS);
        float kl = __ldg(knots + c * K_KNOTS + K_KNOTS - 1);
        float c0 = __ldg(coefs + c * K_KNOTS + j);
        float c1 = __ldg(coefs + c * K_KNOTS + min(j + 1, K_KNOTS - 1));
        float h  = (kl - k0) * (1.0f / (float)N_SEG);
        float tol = 1e-4f * fabsf(h) + 1e-30f;
        float pred = fmaf((float)j, h, k0);
        if (!(h > 0.0f) || fabsf(kj - pred) > tol) bad = true;
        if (j < N_SEG)
            sseg[(j << 8) + COLP(c)] = make_float2(c0, c1 - c0);
        if (j == 0) {  // one writer per channel for params
            float invh = (float)N_SEG / (kl - k0);
            float scale = h / (h + EPS);
            sparam[c] = make_float4(invh, -k0 * invh, scale, 0.0f);
        }
    }
    if (bad) *sflag = 1;       // only 1s written after the 0-init barrier
    __syncthreads();

    const bool affine = (*sflag == 0);

    const float4* __restrict__ u4 = (const float4*)u;
    float4*       __restrict__ o4 = (float4*)out;
    const int gtid   = blockIdx.x * blockDim.x + tid;
    const int stride = blockDim.x * gridDim.x;   // group stride; 8*stride % 256 == 0
    const int cb     = (gtid * 8) & (M_CH - 1);  // channels cb..cb+7, fixed

    if (affine) {
        // preload this thread's 8 channel params into registers
        float p_invh[8], p_b[8], p_scale[8];
        #pragma unroll
        for (int i = 0; i < 8; i++) {
            float4 p = sparam[cb + i];
            p_invh[i] = p.x; p_b[i] = p.y; p_scale[i] = p.z;
        }
        // permuted table base: + (i<<5) + (j<<8) per access; bank-pair = 2*lane
        const float2* __restrict__ seg0 = sseg + (cb >> 3);

        for (int t = gtid; t < n8; t += stride) {
            float4 a = u4[2 * t];
            float4 b = u4[2 * t + 1];
            float x[8] = {a.x, a.y, a.z, a.w, b.x, b.y, b.z, b.w};
            float r[8];
            #pragma unroll
            for (int i = 0; i < 8; i++) {
                float s  = fmaf(x[i], p_invh[i], p_b[i]);
                float jf = floorf(s);
                jf = fminf(fmaxf(jf, 0.0f), (float)(N_SEG - 1));
                int  ji = (int)jf;
                float2 cd = seg0[(ji << 8) + (i << 5)];   // conflict-free LDS.64
                float tt = (s - jf) * p_scale[i];
                r[i] = fmaf(tt, cd.y, cd.x);
            }
            o4[2 * t]     = make_float4(r[0], r[1], r[2], r[3]);
            o4[2 * t + 1] = make_float4(r[4], r[5], r[6], r[7]);
        }
    } else {
        // generic fallback: exact searchsorted-left via binary search, f32 math
        for (int t = gtid; t < n8; t += stride) {
            float4 a = u4[2 * t];
            float4 b = u4[2 * t + 1];
            float x[8] = {a.x, a.y, a.z, a.w, b.x, b.y, b.z, b.w};
            float r[8];
            #pragma unroll
            for (int i = 0; i < 8; i++) {
                const int c = cb + i;
                const float* kc = knots + c * K_KNOTS;
                const float xi = x[i];
                int lo = 0, hi = K_KNOTS;
                while (lo < hi) {
                    int mid = (lo + hi) >> 1;
                    if (__ldg(kc + mid) < xi) lo = mid + 1; else hi = mid;
                }
                int j = min(max(lo - 1, 0), N_SEG - 1);
                float k0 = __ldg(kc + j);
                float k1 = __ldg(kc + j + 1);
                float2 cd = sseg[(j << 8) + COLP(c)];
                float tt = (xi - k0) / (k1 - k0 + EPS);
                r[i] = fmaf(tt, cd.y, cd.x);
            }
            o4[2 * t]     = make_float4(r[0], r[1], r[2], r[3]);
            o4[2 * t + 1] = make_float4(r[4], r[5], r[6], r[7]);
        }
    }
}

extern "C" void kernel_launch(void* const* d_in, const int* in_sizes, int n_in,
                              void* d_out, int out_size)
{
    const float* u     = (const float*)d_in[0];
    const float* knots = (const float*)d_in[1];
    const float* coefs = (const float*)d_in[2];
    float*       out   = (float*)d_out;

    const int n  = in_sizes[0];   // 67,108,864 (divisible by 8)
    const int n8 = n >> 3;

    static_assert(SMEM_BYTES <= 227 * 1024, "smem over sm_103a limit");
    cudaFuncSetAttribute(bspline_kernel,
                         cudaFuncAttributeMaxDynamicSharedMemorySize, SMEM_BYTES);

    int dev = 0, nsm = 148;
    cudaGetDevice(&dev);
    cudaDeviceGetAttribute(&nsm, cudaDevAttrMultiProcessorCount, dev);

    bspline_kernel<<<nsm, 1024, SMEM_BYTES>>>(u, knots, coefs, out, n8);
}

// round 14
// speedup vs baseline: 1.1113x; 1.0138x over previous
#include <cuda_runtime.h>

// BSplineLayer: piecewise-linear spline eval.
// u: [4096, 64, 256] f32 (flat, channel = i % 256)
// knots: [256, 64] sorted ascending per channel; coefs: [256, 64].
// out = c0 + (x-k0)/(k1-k0+1e-6) * (c1-c0), segment via searchsorted-left.
//
// TERMINAL FORM. Measured: 1072 MB compulsory L2 traffic / 98.0us ncu
// = 10.9 TB/s = the sm_103a path-independent LTS cap; every SM-local pipe
// has slack (DRAM 63%, L1 63%, issue 26%). R14 = R13 + streaming cache
// hints (__ldcs/__stcs) on the zero-reuse main-loop traffic, tested in
// isolation this time (R10 confounded them with a regressing prefetch).
//
// Structure: conflict-free permuted fp32 table sseg[(j<<8)+COLP(c)]
// (LDS.64 bank-pair = 2*lane, independent of data-dependent j), 1024x1
// CTA/SM, 8 consecutive elements per thread via 2 front-batched LDG.128,
// registers hold the 8 per-channel affine params; exact binary-search
// fallback if knots are not affine.

#define M_CH    256
#define K_KNOTS 64
#define N_SEG   63
#define EPS     1e-6f

#define COLP(c) (((c) >> 3) + (((c) & 7) << 5))

// smem: float4 sparam[256] | float2 sseg[64*256] permuted | int flag
#define SMEM_BYTES (256 * 16 + 64 * 256 * 8 + 16)

__global__ __launch_bounds__(1024, 1)
void bspline_kernel(const float* __restrict__ u,
                    const float* __restrict__ knots,
                    const float* __restrict__ coefs,
                    float* __restrict__ out,
                    int n8 /* groups of 8 elements */)
{
    extern __shared__ char smem_raw[];
    float4* sparam = (float4*)smem_raw;                       // [256] (invh, b, scale, 0)
    float2* sseg   = (float2*)(smem_raw + 256 * 16);          // [64][256] permuted (c0, dc)
    int*    sflag  = (int*)(smem_raw + 256 * 16 + 64 * 256 * 8);

    const int tid = threadIdx.x;

    if (tid == 0) *sflag = 0;
    __syncthreads();

    // ---- fused staging + fully parallel uniformity check ----
    // one work-item per (c, j): stage sseg[(j<<8)+COLP(c)] and verify
    // knots[c,j] against the channel's affine prediction. All loads issued
    // independently up front (kj, k0, kl, c0, c1) -> two latency rounds.
    bool bad = false;
    for (int i = tid; i < M_CH * K_KNOTS; i += blockDim.x) {
        int c = i >> 6;
        int j = i & 63;
        float kj = __ldg(knots + i);
        float k0 = __ldg(knots + c * K_KNOTS);
        float kl = __ldg(knots + c * K_KNOTS + K_KNOTS - 1);
        float c0 = __ldg(coefs + c * K_KNOTS + j);
        float c1 = __ldg(coefs + c * K_KNOTS + min(j + 1, K_KNOTS - 1));
        float h  = (kl - k0) * (1.0f / (float)N_SEG);
        float tol = 1e-4f * fabsf(h) + 1e-30f;
        float pred = fmaf((float)j, h, k0);
        if (!(h > 0.0f) || fabsf(kj - pred) > tol) bad = true;
        if (j < N_SEG)
            sseg[(j << 8) + COLP(c)] = make_float2(c0, c1 - c0);
        if (j == 0) {  // one writer per channel for params
            float invh = (float)N_SEG / (kl - k0);
            float scale = h / (h + EPS);
            sparam[c] = make_float4(invh, -k0 * invh, scale, 0.0f);
        }
    }
    if (bad) *sflag = 1;       // only 1s written after the 0-init barrier
    __syncthreads();

    const bool affine = (*sflag == 0);

    const float4* __restrict__ u4 = (const float4*)u;
    float4*       __restrict__ o4 = (float4*)out;
    const int gtid   = blockIdx.x * blockDim.x + tid;
    const int stride = blockDim.x * gridDim.x;   // group stride; 8*stride % 256 == 0
    const int cb     = (gtid * 8) & (M_CH - 1);  // channels cb..cb+7, fixed

    if (affine) {
        // preload this thread's 8 channel params into registers
        float p_invh[8], p_b[8], p_scale[8];
        #pragma unroll
        for (int i = 0; i < 8; i++) {
            float4 p = sparam[cb + i];
            p_invh[i] = p.x; p_b[i] = p.y; p_scale[i] = p.z;
        }
        // permuted table base: + (i<<5) + (j<<8) per access; bank-pair = 2*lane
        const float2* __restrict__ seg0 = sseg + (cb >> 3);

        for (int t = gtid; t < n8; t += stride) {
            float4 a = __ldcs(u4 + 2 * t);        // streaming: read-once data
            float4 b = __ldcs(u4 + 2 * t + 1);
            float x[8] = {a.x, a.y, a.z, a.w, b.x, b.y, b.z, b.w};
            float r[8];
            #pragma unroll
            for (int i = 0; i < 8; i++) {
                float s  = fmaf(x[i], p_invh[i], p_b[i]);
                float jf = floorf(s);
                jf = fminf(fmaxf(jf, 0.0f), (float)(N_SEG - 1));
                int  ji = (int)jf;
                float2 cd = seg0[(ji << 8) + (i << 5)];   // conflict-free LDS.64
                float tt = (s - jf) * p_scale[i];
                r[i] = fmaf(tt, cd.y, cd.x);
            }
            __stcs(o4 + 2 * t,     make_float4(r[0], r[1], r[2], r[3]));
            __stcs(o4 + 2 * t + 1, make_float4(r[4], r[5], r[6], r[7]));
        }
    } else {
        // generic fallback: exact searchsorted-left via binary search, f32 math
        for (int t = gtid; t < n8; t += stride) {
            float4 a = u4[2 * t];
            float4 b = u4[2 * t + 1];
            float x[8] = {a.x, a.y, a.z, a.w, b.x, b.y, b.z, b.w};
            float r[8];
            #pragma unroll
            for (int i = 0; i < 8; i++) {
                const int c = cb + i;
                const float* kc = knots + c * K_KNOTS;
                const float xi = x[i];
                int lo = 0, hi = K_KNOTS;
                while (lo < hi) {
                    int mid = (lo + hi) >> 1;
                    if (__ldg(kc + mid) < xi) lo = mid + 1; else hi = mid;
                }
                int j = min(max(lo - 1, 0), N_SEG - 1);
                float k0 = __ldg(kc + j);
                float k1 = __ldg(kc + j + 1);
                float2 cd = sseg[(j << 8) + COLP(c)];
                float tt = (xi - k0) / (k1 - k0 + EPS);
                r[i] = fmaf(tt, cd.y, cd.x);
            }
            o4[2 * t]     = make_float4(r[0], r[1], r[2], r[3]);
            o4[2 * t + 1] = make_float4(r[4], r[5], r[6], r[7]);
        }
    }
}

extern "C" void kernel_launch(void* const* d_in, const int* in_sizes, int n_in,
                              void* d_out, int out_size)
{
    const float* u     = (const float*)d_in[0];
    const float* knots = (const float*)d_in[1];
    const float* coefs = (const float*)d_in[2];
    float*       out   = (float*)d_out;

    const int n  = in_sizes[0];   // 67,108,864 (divisible by 8)
    const int n8 = n >> 3;

    static_assert(SMEM_BYTES <= 227 * 1024, "smem over sm_103a limit");
    cudaFuncSetAttribute(bspline_kernel,
                         cudaFuncAttributeMaxDynamicSharedMemorySize, SMEM_BYTES);

    int dev = 0, nsm = 148;
    cudaGetDevice(&dev);
    cudaDeviceGetAttribute(&nsm, cudaDevAttrMultiProcessorCount, dev);

    bspline_kernel<<<nsm, 1024, SMEM_BYTES>>>(u, knots, coefs, out, n8);
}

// round 15
// speedup vs baseline: 1.1518x; 1.0365x over previous
#include <cuda_runtime.h>

// BSplineLayer: piecewise-linear spline eval.
// u: [4096, 64, 256] f32 (flat, channel = i % 256)
// knots: [256, 64] sorted ascending per channel; coefs: [256, 64].
// out = c0 + (x-k0)/(k1-k0+1e-6) * (c1-c0), segment via searchsorted-left.
//
// TERMINAL FORM (session: 297.5 -> ~101 us, ~2.9x).
// Measured: 1072 MB compulsory combined L2 traffic / ~99us = ~10.8 TB/s,
// the sm_103a path-independent LTS cap. All SM-local pipes have slack;
// all structural levers tested and closed (conflicts R9: flat, MLP R10:
// flat, warps R5-R7: worse, icount R11: flat, prologue R12/13: -4us,
// streaming hints R14: -1.4us).
//
// Structure: conflict-free permuted fp32 table sseg[(j<<8)+COLP(c)]
// (LDS.64 bank-pair = 2*lane, independent of data-dependent j), 1024x1
// CTA/SM, 8 consecutive elements per thread via 2 front-batched LDG.128
// with __ldcs/__stcs streaming, per-channel affine params in registers;
// exact binary-search fallback if knots are not affine.

#define M_CH    256
#define K_KNOTS 64
#define N_SEG   63
#define EPS     1e-6f

#define COLP(c) (((c) >> 3) + (((c) & 7) << 5))

// smem: float2 sparam[256] (invh,b) | float sscale[256] | float2 sseg[64*256] | int flag
#define SMEM_BYTES (256 * 8 + 256 * 4 + 64 * 256 * 8 + 16)

__global__ __launch_bounds__(1024, 1)
void bspline_kernel(const float* __restrict__ u,
                    const float* __restrict__ knots,
                    const float* __restrict__ coefs,
                    float* __restrict__ out,
                    int n8 /* groups of 8 elements */)
{
    extern __shared__ char smem_raw[];
    float2* sparam = (float2*)smem_raw;                          // [256] (invh, b)
    float*  sscale = (float*)(smem_raw + 256 * 8);               // [256] scale
    float2* sseg   = (float2*)(smem_raw + 256 * 8 + 256 * 4);    // [64][256] permuted
    int*    sflag  = (int*)(smem_raw + 256 * 8 + 256 * 4 + 64 * 256 * 8);

    const int tid = threadIdx.x;

    if (tid == 0) *sflag = 0;
    __syncthreads();

    // ---- fused staging + fully parallel uniformity check ----
    // one work-item per (c, j): stage sseg[(j<<8)+COLP(c)] and verify
    // knots[c,j] against the channel's affine prediction. All loads issued
    // independently up front -> two latency rounds total.
    bool bad = false;
    for (int i = tid; i < M_CH * K_KNOTS; i += blockDim.x) {
        int c = i >> 6;
        int j = i & 63;
        float kj = __ldg(knots + i);
        float k0 = __ldg(knots + c * K_KNOTS);
        float kl = __ldg(knots + c * K_KNOTS + K_KNOTS - 1);
        float c0 = __ldg(coefs + c * K_KNOTS + j);
        float c1 = __ldg(coefs + c * K_KNOTS + min(j + 1, K_KNOTS - 1));
        float h  = (kl - k0) * (1.0f / (float)N_SEG);
        float tol = 1e-4f * fabsf(h) + 1e-30f;
        float pred = fmaf((float)j, h, k0);
        if (!(h > 0.0f) || fabsf(kj - pred) > tol) bad = true;
        if (j < N_SEG)
            sseg[(j << 8) + COLP(c)] = make_float2(c0, c1 - c0);
        if (j == 0) {  // one writer per channel; reuses k0/kl already in regs
            float invh = (float)N_SEG / (kl - k0);
            sparam[c] = make_float2(invh, -k0 * invh);
            sscale[c] = h / (h + EPS);
        }
    }
    if (bad) *sflag = 1;       // only 1s written after the 0-init barrier
    __syncthreads();

    const bool affine = (*sflag == 0);

    const float4* __restrict__ u4 = (const float4*)u;
    float4*       __restrict__ o4 = (float4*)out;
    const int gtid   = blockIdx.x * blockDim.x + tid;
    const int stride = blockDim.x * gridDim.x;   // group stride; 8*stride % 256 == 0
    const int cb     = (gtid * 8) & (M_CH - 1);  // channels cb..cb+7, fixed

    if (affine) {
        // preload this thread's 8 channel params into registers
        float p_invh[8], p_b[8], p_scale[8];
        #pragma unroll
        for (int i = 0; i < 8; i++) {
            float2 p = sparam[cb + i];
            p_invh[i] = p.x; p_b[i] = p.y;
            p_scale[i] = sscale[cb + i];
        }
        // permuted table base: + (i<<5) + (j<<8) per access; bank-pair = 2*lane
        const float2* __restrict__ seg0 = sseg + (cb >> 3);

        for (int t = gtid; t < n8; t += stride) {
            float4 a = __ldcs(u4 + 2 * t);        // streaming: read-once data
            float4 b = __ldcs(u4 + 2 * t + 1);
            float x[8] = {a.x, a.y, a.z, a.w, b.x, b.y, b.z, b.w};
            float r[8];
            #pragma unroll
            for (int i = 0; i < 8; i++) {
                float s  = fmaf(x[i], p_invh[i], p_b[i]);
                float jf = floorf(s);
                jf = fminf(fmaxf(jf, 0.0f), (float)(N_SEG - 1));
                int  ji = (int)jf;
                float2 cd = seg0[(ji << 8) + (i << 5)];   // conflict-free LDS.64
                float tt = (s - jf) * p_scale[i];
                r[i] = fmaf(tt, cd.y, cd.x);
            }
            __stcs(o4 + 2 * t,     make_float4(r[0], r[1], r[2], r[3]));
            __stcs(o4 + 2 * t + 1, make_float4(r[4], r[5], r[6], r[7]));
        }
    } else {
        // generic fallback: exact searchsorted-left via binary search, f32 math
        for (int t = gtid; t < n8; t += stride) {
            float4 a = u4[2 * t];
            float4 b = u4[2 * t + 1];
            float x[8] = {a.x, a.y, a.z, a.w, b.x, b.y, b.z, b.w};
            float r[8];
            #pragma unroll
            for (int i = 0; i < 8; i++) {
                const int c = cb + i;
                const float* kc = knots + c * K_KNOTS;
                const float xi = x[i];
                int lo = 0, hi = K_KNOTS;
                while (lo < hi) {
                    int mid = (lo + hi) >> 1;
                    if (__ldg(kc + mid) < xi) lo = mid + 1; else hi = mid;
                }
                int j = min(max(lo - 1, 0), N_SEG - 1);
                float k0 = __ldg(kc + j);
                float k1 = __ldg(kc + j + 1);
                float2 cd = sseg[(j << 8) + COLP(c)];
                float tt = (xi - k0) / (k1 - k0 + EPS);
                r[i] = fmaf(tt, cd.y, cd.x);
            }
            o4[2 * t]     = make_float4(r[0], r[1], r[2], r[3]);
            o4[2 * t + 1] = make_float4(r[4], r[5], r[6], r[7]);
        }
    }
}

extern "C" void kernel_launch(void* const* d_in, const int* in_sizes, int n_in,
                              void* d_out, int out_size)
{
    const float* u     = (const float*)d_in[0];
    const float* knots = (const float*)d_in[1];
    const float* coefs = (const float*)d_in[2];
    float*       out   = (float*)d_out;

    const int n  = in_sizes[0];   // 67,108,864 (divisible by 8)
    const int n8 = n >> 3;

    static_assert(SMEM_BYTES <= 227 * 1024, "smem over sm_103a limit");
    cudaFuncSetAttribute(bspline_kernel,
                         cudaFuncAttributeMaxDynamicSharedMemorySize, SMEM_BYTES);

    int dev = 0, nsm = 148;
    cudaGetDevice(&dev);
    cudaDeviceGetAttribute(&nsm, cudaDevAttrMultiProcessorCount, dev);

    bspline_kernel<<<nsm, 1024, SMEM_BYTES>>>(u, knots, coefs, out, n8);
}

// round 16
// speedup vs baseline: 1.1690x; 1.0149x over previous
#include <cuda_runtime.h>

// BSplineLayer: piecewise-linear spline eval.
// u: [4096, 64, 256] f32 (flat, channel = i % 256)
// knots: [256, 64] sorted ascending per channel; coefs: [256, 64].
// out = c0 + (x-k0)/(k1-k0+1e-6) * (c1-c0), segment via searchsorted-left.
//
// TERMINAL FORM (session: 297.5 -> 98.2 us, 3.03x).
// Measured: 1072 MB compulsory combined L2 traffic / 98.3us ncu = 10.9 TB/s
// = the sm_103a path-independent LTS chip cap. All SM-local pipes have
// slack (DRAM 62%, L1 60%, issue 26%); all structural levers tested and
// closed: LDS conflicts (R9: flat), per-warp MLP (R10: flat), warp count
// (R5-R7: worse), icount (R11: flat), prologue (R12/13/15: -6us),
// streaming hints (R14: -1.4us). Grid-stride imbalance is 0.2% (54 vs
// 53.9 iters). Both byte streams are compulsory; this is the roofline.
//
// Structure: conflict-free permuted fp32 table sseg[(j<<8)+COLP(c)]
// (LDS.64 bank-pair = 2*lane, independent of data-dependent j), 1024x1
// CTA/SM, 8 consecutive elements per thread via 2 front-batched LDG.128
// with __ldcs/__stcs streaming, per-channel affine params in registers;
// exact binary-search fallback if knots are not affine.

#define M_CH    256
#define K_KNOTS 64
#define N_SEG   63
#define EPS     1e-6f

#define COLP(c) (((c) >> 3) + (((c) & 7) << 5))

// smem: float2 sparam[256] (invh,b) | float sscale[256] | float2 sseg[64*256] | int flag
#define SMEM_BYTES (256 * 8 + 256 * 4 + 64 * 256 * 8 + 16)

__global__ __launch_bounds__(1024, 1)
void bspline_kernel(const float* __restrict__ u,
                    const float* __restrict__ knots,
                    const float* __restrict__ coefs,
                    float* __restrict__ out,
                    int n8 /* groups of 8 elements */)
{
    extern __shared__ char smem_raw[];
    float2* sparam = (float2*)smem_raw;                          // [256] (invh, b)
    float*  sscale = (float*)(smem_raw + 256 * 8);               // [256] scale
    float2* sseg   = (float2*)(smem_raw + 256 * 8 + 256 * 4);    // [64][256] permuted
    int*    sflag  = (int*)(smem_raw + 256 * 8 + 256 * 4 + 64 * 256 * 8);

    const int tid = threadIdx.x;

    if (tid == 0) *sflag = 0;
    __syncthreads();

    // ---- fused staging + fully parallel uniformity check ----
    // one work-item per (c, j): stage sseg[(j<<8)+COLP(c)] and verify
    // knots[c,j] against the channel's affine prediction. All loads issued
    // independently up front -> two latency rounds total.
    bool bad = false;
    for (int i = tid; i < M_CH * K_KNOTS; i += blockDim.x) {
        int c = i >> 6;
        int j = i & 63;
        float kj = __ldg(knots + i);
        float k0 = __ldg(knots + c * K_KNOTS);
        float kl = __ldg(knots + c * K_KNOTS + K_KNOTS - 1);
        float c0 = __ldg(coefs + c * K_KNOTS + j);
        float c1 = __ldg(coefs + c * K_KNOTS + min(j + 1, K_KNOTS - 1));
        float h  = (kl - k0) * (1.0f / (float)N_SEG);
        float tol = 1e-4f * fabsf(h) + 1e-30f;
        float pred = fmaf((float)j, h, k0);
        if (!(h > 0.0f) || fabsf(kj - pred) > tol) bad = true;
        if (j < N_SEG)
            sseg[(j << 8) + COLP(c)] = make_float2(c0, c1 - c0);
        if (j == 0) {  // one writer per channel; reuses k0/kl already in regs
            float invh = (float)N_SEG / (kl - k0);
            sparam[c] = make_float2(invh, -k0 * invh);
            sscale[c] = h / (h + EPS);
        }
    }
    if (bad) *sflag = 1;       // only 1s written after the 0-init barrier
    __syncthreads();

    const bool affine = (*sflag == 0);

    const float4* __restrict__ u4 = (const float4*)u;
    float4*       __restrict__ o4 = (float4*)out;
    const int gtid   = blockIdx.x * blockDim.x + tid;
    const int stride = blockDim.x * gridDim.x;   // group stride; 8*stride % 256 == 0
    const int cb     = (gtid * 8) & (M_CH - 1);  // channels cb..cb+7, fixed

    if (affine) {
        // preload this thread's 8 channel params into registers
        float p_invh[8], p_b[8], p_scale[8];
        #pragma unroll
        for (int i = 0; i < 8; i++) {
            float2 p = sparam[cb + i];
            p_invh[i] = p.x; p_b[i] = p.y;
            p_scale[i] = sscale[cb + i];
        }
        // permuted table base: + (i<<5) + (j<<8) per access; bank-pair = 2*lane
        const float2* __restrict__ seg0 = sseg + (cb >> 3);

        for (int t = gtid; t < n8; t += stride) {
            float4 a = __ldcs(u4 + 2 * t);        // streaming: read-once data
            float4 b = __ldcs(u4 + 2 * t + 1);
            float x[8] = {a.x, a.y, a.z, a.w, b.x, b.y, b.z, b.w};
            float r[8];
            #pragma unroll
            for (int i = 0; i < 8; i++) {
                float s  = fmaf(x[i], p_invh[i], p_b[i]);
                float jf = floorf(s);
                jf = fminf(fmaxf(jf, 0.0f), (float)(N_SEG - 1));
                int  ji = (int)jf;
                float2 cd = seg0[(ji << 8) + (i << 5)];   // conflict-free LDS.64
                float tt = (s - jf) * p_scale[i];
                r[i] = fmaf(tt, cd.y, cd.x);
            }
            __stcs(o4 + 2 * t,     make_float4(r[0], r[1], r[2], r[3]));
            __stcs(o4 + 2 * t + 1, make_float4(r[4], r[5], r[6], r[7]));
        }
    } else {
        // generic fallback: exact searchsorted-left via binary search, f32 math
        for (int t = gtid; t < n8; t += stride) {
            float4 a = u4[2 * t];
            float4 b = u4[2 * t + 1];
            float x[8] = {a.x, a.y, a.z, a.w, b.x, b.y, b.z, b.w};
            float r[8];
            #pragma unroll
            for (int i = 0; i < 8; i++) {
                const int c = cb + i;
                const float* kc = knots + c * K_KNOTS;
                const float xi = x[i];
                int lo = 0, hi = K_KNOTS;
                while (lo < hi) {
                    int mid = (lo + hi) >> 1;
                    if (__ldg(kc + mid) < xi) lo = mid + 1; else hi = mid;
                }
                int j = min(max(lo - 1, 0), N_SEG - 1);
                float k0 = __ldg(kc + j);
                float k1 = __ldg(kc + j + 1);
                float2 cd = sseg[(j << 8) + COLP(c)];
                float tt = (xi - k0) / (k1 - k0 + EPS);
                r[i] = fmaf(tt, cd.y, cd.x);
            }
            o4[2 * t]     = make_float4(r[0], r[1], r[2], r[3]);
            o4[2 * t + 1] = make_float4(r[4], r[5], r[6], r[7]);
        }
    }
}

extern "C" void kernel_launch(void* const* d_in, const int* in_sizes, int n_in,
                              void* d_out, int out_size)
{
    const float* u     = (const float*)d_in[0];
    const float* knots = (const float*)d_in[1];
    const float* coefs = (const float*)d_in[2];
    float*       out   = (float*)d_out;

    const int n  = in_sizes[0];   // 67,108,864 (divisible by 8)
    const int n8 = n >> 3;

    static_assert(SMEM_BYTES <= 227 * 1024, "smem over sm_103a limit");
    cudaFuncSetAttribute(bspline_kernel,
                         cudaFuncAttributeMaxDynamicSharedMemorySize, SMEM_BYTES);

    int dev = 0, nsm = 148;
    cudaGetDevice(&dev);
    cudaDeviceGetAttribute(&nsm, cudaDevAttrMultiProcessorCount, dev);

    bspline_kernel<<<nsm, 1024, SMEM_BYTES>>>(u, knots, coefs, out, n8);
}